// round 2
// baseline (speedup 1.0000x reference)
#include <cuda_runtime.h>
#include <cstdint>

// TaylorExp: out[row] = [1, x/sqrt(sqrt(d)), (x_i*x_j)/(sqrt(2)*sqrt(d))]
// d = 16 -> 273 floats per row. rows = in_sizes[0] / 16.
//
// One warp per row computes into SMEM (register-broadcast via shfl,
// conflict-free scalar STS). Then the whole block streams its contiguous
// 8-row output region (8736 B, 16B-aligned) to GMEM with float4 stores.

#define D 16
#define OUT_PER_ROW 273
#define ROWS_PER_BLOCK 8
#define THREADS 256
#define FULL 0xffffffffu

#define BLOCK_FLOATS (ROWS_PER_BLOCK * OUT_PER_ROW)   // 2184
#define BLOCK_VEC4   (BLOCK_FLOATS / 4)               // 546 (exact)

__global__ __launch_bounds__(THREADS)
void taylor_exp_kernel(const float* __restrict__ x,
                       float* __restrict__ out,
                       int rows) {
    __shared__ float sbuf[BLOCK_FLOATS];

    const int warp = threadIdx.x >> 5;
    const int lane = threadIdx.x & 31;
    const int base_row = blockIdx.x * ROWS_PER_BLOCK;
    const int row = base_row + warp;

    // ---- compute phase: one warp per row -> smem ----
    if (row < rows) {
        float xv = 0.0f;
        if (lane < D) xv = x[(size_t)row * D + lane];

        const float s_lin  = 0.5f;                  // 1/sqrt(sqrt(16))
        const float s_quad = 0.17677669529663689f;  // 1/(sqrt(2)*sqrt(16))

        float* so = sbuf + warp * OUT_PER_ROW;

        #pragma unroll
        for (int it = 0; it < 9; ++it) {
            const int idx = it * 32 + lane;
            const int k = idx - 17;
            const float xl = __shfl_sync(FULL, xv, (idx - 1) & 15);
            const float xi = __shfl_sync(FULL, xv, (k >> 4) & 15);
            const float xj = __shfl_sync(FULL, xv, k & 15);

            float v = xi * xj * s_quad;
            if (idx < 17) v = xl * s_lin;
            if (idx == 0) v = 1.0f;

            if (idx < OUT_PER_ROW) so[idx] = v;
        }
    }
    __syncthreads();

    // ---- store phase: vectorized float4 copy of the block's region ----
    const size_t blk_base = (size_t)base_row * OUT_PER_ROW;

    if (base_row + ROWS_PER_BLOCK <= rows) {
        // full block: region is 16B-aligned and size % 16 == 0
        float4* __restrict__ o4 = reinterpret_cast<float4*>(out + blk_base);
        const float4* __restrict__ s4 = reinterpret_cast<const float4*>(sbuf);
        #pragma unroll
        for (int i = threadIdx.x; i < BLOCK_VEC4; i += THREADS) {
            o4[i] = s4[i];
        }
    } else {
        // tail block (unused for the bench shape): scalar copy of valid rows
        const int valid = (rows - base_row) * OUT_PER_ROW;
        for (int i = threadIdx.x; i < valid; i += THREADS) {
            out[blk_base + i] = sbuf[i];
        }
    }
}

extern "C" void kernel_launch(void* const* d_in, const int* in_sizes, int n_in,
                              void* d_out, int out_size) {
    const float* x = (const float*)d_in[0];
    float* out = (float*)d_out;

    const int rows = in_sizes[0] / D;   // 262144 for the bench shape
    const int blocks = (rows + ROWS_PER_BLOCK - 1) / ROWS_PER_BLOCK;

    taylor_exp_kernel<<<blocks, THREADS>>>(x, out, rows);
}

// round 3
// speedup vs baseline: 1.1722x; 1.1722x over previous
#include <cuda_runtime.h>
#include <cstdint>

// TaylorExp: out[row] = [1, x/sqrt(sqrt(d)), (x_i*x_j)/(sqrt(2)*sqrt(d))]
// d = 16 -> 273 floats per row. rows = in_sizes[0] / 16.
//
// One warp per TWO rows: lanes 0..15 hold row A, lanes 16..31 hold row B
// (full 128B coalesced load). Exploits 32 % 16 == 0: the j-index (k & 15)
// is constant across output sweeps -> 1 shuffle; i-index advances by 2 per
// sweep -> 1 shuffle per sweep. 11 shuffles/row vs 27 in the naive version.

#define D 16
#define OUT_PER_ROW 273
#define FULL 0xffffffffu

__global__ __launch_bounds__(256)
void taylor_exp_kernel(const float* __restrict__ x,
                       float* __restrict__ out,
                       int rows) {
    const int gwarp = (blockIdx.x * blockDim.x + threadIdx.x) >> 5;
    const int lane  = threadIdx.x & 31;
    const int r0 = gwarp * 2;
    if (r0 >= rows) return;

    // Coalesced 128B load of two rows; guard the tail element-wise.
    float xv = 0.0f;
    {
        const size_t e = (size_t)r0 * D + lane;
        if (e < (size_t)rows * D) xv = x[e];
    }

    const float s_lin  = 0.5f;                  // 1/sqrt(sqrt(16))
    const float s_quad = 0.17677669529663689f;  // 1/(sqrt(2)*sqrt(16))

    // Iteration-invariant shuffle operands.
    const int ilo  = (lane + 15) >> 4;          // 0,1,2
    const int jrel = (lane + 15) & 15;          // j = k & 15, constant over sweeps

    const float xlA = __shfl_sync(FULL, xv, (lane - 1) & 15);
    const float xjA = __shfl_sync(FULL, xv, jrel);
    const float xlB = __shfl_sync(FULL, xv, 16 + ((lane - 1) & 15));
    const float xjB = __shfl_sync(FULL, xv, 16 + jrel);

    float* __restrict__ oA = out + (size_t)r0 * OUT_PER_ROW;
    float* __restrict__ oB = oA + OUT_PER_ROW;
    const bool hasB = (r0 + 1) < rows;

    #pragma unroll
    for (int it = 0; it < 9; ++it) {
        // i = k >> 4 = 2*(it-1) + ilo for the quadratic region (valid lanes).
        const int i = (2 * it - 2 + ilo) & 15;
        const float xiA = __shfl_sync(FULL, xv, i);
        const float xiB = __shfl_sync(FULL, xv, 16 + i);

        float vA = xiA * xjA * s_quad;
        float vB = xiB * xjB * s_quad;

        if (it == 0) {                 // compile-time branch (unrolled)
            if (lane < 17) { vA = xlA * s_lin; vB = xlB * s_lin; }
            if (lane == 0) { vA = 1.0f; vB = 1.0f; }
        }

        const int idx = it * 32 + lane;
        if (idx < OUT_PER_ROW) {
            oA[idx] = vA;
            if (hasB) oB[idx] = vB;
        }
    }
}

extern "C" void kernel_launch(void* const* d_in, const int* in_sizes, int n_in,
                              void* d_out, int out_size) {
    const float* x = (const float*)d_in[0];
    float* out = (float*)d_out;

    const int rows  = in_sizes[0] / D;          // 262144 for the bench shape
    const int warps = (rows + 1) / 2;
    const int threads = 256;
    const int blocks = (warps * 32 + threads - 1) / threads;

    taylor_exp_kernel<<<blocks, threads>>>(x, out, rows);
}